// round 7
// baseline (speedup 1.0000x reference)
#include <cuda_runtime.h>
#include <math.h>

#define NROWS 32
#define NCOLS 512
#define NPAIRS 130816            // 512*511/2
#define CHUNKS 32
#define PAIRS_PER_CHUNK (NPAIRS / CHUNKS)   // 4088 (exact)
#define TOTAL_BLOCKS (CHUNKS * NROWS)       // 1024
#define TSTW 256                 // tau / w merged table size, domain [0,1]
#define TSG 1024                 // g table size
#define G_MIN (-24.0f)
#define G_RANGE 64.0f            // g domain [-24, 40]
#define NB_TAU 8
#define NB_G 8
#define NB_W 6
#define W_FLOOR 0.001f

// ---------------- device scratch (no allocations allowed) ----------------
__device__ float4 d_tab_tw[TSTW];              // (tau0, dtau, w0, dw)
__device__ float2 d_tab_g[TSG];                // (g0, dg)
__device__ float  d_part_sum[TOTAL_BLOCKS];    // per-block partials (always written)
__device__ int    d_part_cnt[TOTAL_BLOCKS];
__device__ int    d_done;                      // last-block-done counter (reset by last block)

// fast-math activations (table build only; rel_err budget ~1e-3, measured 2e-7)
__device__ __forceinline__ float fsp(float z) {
    return fmaxf(z, 0.0f) + __logf(1.0f + __expf(-fabsf(z)));
}
__device__ __forceinline__ float fsg(float z) {
    return __fdividef(1.0f, 1.0f + __expf(-z));
}

// ---------------- kernel A: build lerp tables ----------------
__global__ void __launch_bounds__(256) table_kernel(
    const float* __restrict__ th_tau, const float* __restrict__ th_g,
    const float* __restrict__ th_w)
{
    int e = blockIdx.x * 256 + threadIdx.x;   // 0 .. TSTW+TSG-1 (= 1279)
    if (e < TSTW) {
        float ct[NB_TAU], cw[NB_W];
#pragma unroll
        for (int i = 0; i < NB_TAU; i++) ct[i] = fsp(th_tau[i]);
#pragma unroll
        for (int i = 0; i < NB_W; i++)   cw[i] = fsp(th_w[i]);
        float h = 1.0f / (float)(TSTW - 1);
        float x = (float)e * h;
        float t0 = 0.f, t1 = 0.f, w0 = 0.f, w1 = 0.f;
#pragma unroll
        for (int i = 0; i < NB_TAU; i++) {
            float sl = 0.5f + 3.5f * (float)i / (float)(NB_TAU - 1);
            float bi = -2.0f + 4.0f * (float)i / (float)(NB_TAU - 1);
            t0 += ct[i] * fsp(fmaf(x,     sl, bi));
            t1 += ct[i] * fsp(fmaf(x + h, sl, bi));
        }
#pragma unroll
        for (int i = 0; i < NB_W; i++) {
            float sl = 0.5f + 3.5f * (float)i / (float)(NB_W - 1);
            float bi = -2.0f + 4.0f * (float)i / (float)(NB_W - 1);
            w0 += cw[i] * fsg(fmaf(x,     sl, bi));
            w1 += cw[i] * fsg(fmaf(x + h, sl, bi));
        }
        d_tab_tw[e] = make_float4(t0, t1 - t0, w0, w1 - w0);
    } else if (e < TSTW + TSG) {
        int i = e - TSTW;
        float cg[NB_G];
#pragma unroll
        for (int u = 0; u < NB_G; u++) cg[u] = fsp(th_g[u]);
        float h = G_RANGE / (float)(TSG - 1);
        float x = G_MIN + (float)i * h;
        float v0 = 0.f, v1 = 0.f;
#pragma unroll
        for (int u = 0; u < NB_G; u++) {
            float sl = 0.5f + 3.5f * (float)u / (float)(NB_G - 1);
            float bi = -2.0f + 4.0f * (float)u / (float)(NB_G - 1);
            v0 += cg[u] * fsp(fmaf(x,     sl, bi));
            v1 += cg[u] * fsp(fmaf(x + h, sl, bi));
        }
        d_tab_g[i] = make_float2(v0, v1 - v0);
    }
}

// ---------------- kernel B: normalization + pair loop + final (fused) --------
__global__ void __launch_bounds__(256) pair_kernel(
    const float* __restrict__ pred, const float* __restrict__ tg,
    float* __restrict__ out)
{
    __shared__ float2 sh_g[TSG];       // 8 KB
    __shared__ float4 sh_tw[TSTW];     // 4 KB
    __shared__ float2 sh_rs[NCOLS];    // 4 KB  (r or NaN-if-masked, s)
    __shared__ float  red_f[8];
    __shared__ float  red_f2[8];
    __shared__ int    red_i[8];
    __shared__ float  bcast[2];
    __shared__ int    sh_last;
    __shared__ float  s_num[32];
    __shared__ float  s_val[32];

    int tid  = threadIdx.x;
    int b    = blockIdx.y;
    int lane = tid & 31, warp = tid >> 5;

    // ---- load this row (2 elems/thread) ----
    const float* tr = tg   + b * NCOLS;
    const float* pr = pred + b * NCOLS;
    float t0 = tr[tid], t1 = tr[tid + 256];
    float p0 = pr[tid], p1 = pr[tid + 256];
    bool  m0 = fabsf(t0 + 1.0f) > 1.00001e-5f;   // ~jnp.isclose(t,-1) negated
    bool  m1 = fabsf(t1 + 1.0f) > 1.00001e-5f;

    // ---- table copy gmem -> smem (overlaps with reduction latency) ----
    {
        const float4* sg = (const float4*)d_tab_g;   float4* dg = (float4*)sh_g;
        dg[tid]       = sg[tid];
        dg[tid + 256] = sg[tid + 256];
        sh_tw[tid]    = d_tab_tw[tid];
    }

    // ---- one-pass masked mean / var (block reduction) ----
    float sum = (m0 ? p0 : 0.f) + (m1 ? p1 : 0.f);
    float ssq = (m0 ? p0 * p0 : 0.f) + (m1 ? p1 * p1 : 0.f);
    int   cnt = (int)m0 + (int)m1;
#pragma unroll
    for (int o = 16; o; o >>= 1) {
        sum += __shfl_xor_sync(0xffffffffu, sum, o);
        ssq += __shfl_xor_sync(0xffffffffu, ssq, o);
        cnt += __shfl_xor_sync(0xffffffffu, cnt, o);
    }
    if (lane == 0) { red_f[warp] = sum; red_f2[warp] = ssq; red_i[warp] = cnt; }
    __syncthreads();
    if (tid == 0) {
        float s = 0.f, q = 0.f; int c = 0;
#pragma unroll
        for (int u = 0; u < 8; u++) { s += red_f[u]; q += red_f2[u]; c += red_i[u]; }
        float denom = fmaxf((float)c, 1.0f);
        float mean  = s / denom;
        float var   = q / denom - mean * mean;
        bcast[0] = mean;
        bcast[1] = rsqrtf(var + 1e-6f);
    }
    __syncthreads();
    float mean = bcast[0], inv = bcast[1];
    const float qnan = __int_as_float(0x7fffffff);
    sh_rs[tid]       = make_float2(m0 ? t0 : qnan, (p0 - mean) * inv);
    sh_rs[tid + 256] = make_float2(m1 ? t1 : qnan, (p1 - mean) * inv);
    __syncthreads();

    // ---- pair loop ----
    const float inv_hg = (float)(TSG - 1) / G_RANGE;
    int start = blockIdx.x * PAIRS_PER_CHUNK;
    int end   = start + PAIRS_PER_CHUNK;

    float acc = 0.0f; int pcnt = 0;
#pragma unroll 4
    for (int k = start + tid; k < end; k += 256) {
        // balanced triangular decode: rows v and 510-v folded to length 512
        int v   = k >> 9;
        int off = k & 511;
        int lim = 511 - v;
        int i = (off < lim) ? v           : 510 - v;
        int j = (off < lim) ? v + 1 + off : off;

        float2 pi = sh_rs[i];   // broadcast across warp (usually uniform v)
        float2 pj = sh_rs[j];   // consecutive, conflict-free
        float dr = pi.x - pj.x;
        float ds = pi.y - pj.y;
        bool pos = dr > 0.0f, neg = dr < 0.0f;
        if (pos | neg) {                        // drops ties and NaN (masked)
            float adr = fabsf(dr);
            float tds = pos ? ds : -ds;         // t * ds

            float pt = fminf(adr, 1.0f) * (float)(TSTW - 1);
            int   it = min((int)pt, TSTW - 2);
            float ft = pt - (float)it;
            float4 etw = sh_tw[it];             // one LDS.128: tau + w
            float tau = fmaf(ft, etw.y, etw.x);
            float w   = W_FLOOR + fmaf(ft, etw.w, etw.z);

            float m  = tau - tds;
            float pg = fmaxf((m - G_MIN) * inv_hg, 0.0f);
            int   ig = min((int)pg, TSG - 2);
            float fg = pg - (float)ig;          // frac>1 at top = exact linear ext
            float2 eg = sh_g[ig];
            float g  = fmaf(fg, eg.y, eg.x);

            acc += g * w;
            pcnt += 1;
        }
    }

#pragma unroll
    for (int o = 16; o; o >>= 1) {
        acc  += __shfl_xor_sync(0xffffffffu, acc, o);
        pcnt += __shfl_xor_sync(0xffffffffu, pcnt, o);
    }
    __syncthreads();   // red_f / red_i reuse
    if (lane == 0) { red_f[warp] = acc; red_i[warp] = pcnt; }
    __syncthreads();
    if (tid == 0) {
        float bs = 0.0f; int bc = 0;
#pragma unroll
        for (int u = 0; u < 8; u++) { bs += red_f[u]; bc += red_i[u]; }
        int slot = b * CHUNKS + blockIdx.x;
        d_part_sum[slot] = bs;
        d_part_cnt[slot] = bc;
        __threadfence();
        int old = atomicAdd(&d_done, 1);
        sh_last = (old == TOTAL_BLOCKS - 1) ? 1 : 0;
    }
    __syncthreads();

    // ---- last block performs the final reduction (1024 partials) ----
    if (sh_last) {
        __threadfence();   // acquire: partials of all other blocks now visible
        volatile float* vs = d_part_sum;
        volatile int*   vc = d_part_cnt;
        int row  = tid >> 3;           // 32 rows x 8 lanes, 4 partials each
        int sub  = tid & 7;
        int base = row * CHUNKS + sub * 4;
        float ps = vs[base] + vs[base + 1] + vs[base + 2] + vs[base + 3];
        int   pc = vc[base] + vc[base + 1] + vc[base + 2] + vc[base + 3];
#pragma unroll
        for (int o = 4; o; o >>= 1) {
            ps += __shfl_xor_sync(0xffffffffu, ps, o);
            pc += __shfl_xor_sync(0xffffffffu, pc, o);
        }
        if (sub == 0) {
            float denom = fmaxf((float)pc, 1.0f);
            float rl    = ps / denom;
            float valid = (pc > 0) ? 1.0f : 0.0f;
            s_num[row] = rl * valid;
            s_val[row] = valid;
        }
        __syncthreads();
        if (tid < 32) {
            float n = s_num[tid], v = s_val[tid];
#pragma unroll
            for (int o = 16; o; o >>= 1) {
                n += __shfl_xor_sync(0xffffffffu, n, o);
                v += __shfl_xor_sync(0xffffffffu, v, o);
            }
            if (tid == 0) {
                out[0] = n / fmaxf(v, 1.0f);
                d_done = 0;            // reset for next graph replay (deterministic)
            }
        }
    }
}

// ---------------- launch ----------------
extern "C" void kernel_launch(void* const* d_in, const int* in_sizes, int n_in,
                              void* d_out, int out_size) {
    const float* pred   = (const float*)d_in[0];
    const float* tg     = (const float*)d_in[1];
    const float* th_tau = (const float*)d_in[2];
    const float* th_g   = (const float*)d_in[3];
    const float* th_w   = (const float*)d_in[4];

    table_kernel<<<(TSTW + TSG) / 256, 256>>>(th_tau, th_g, th_w);
    dim3 grid(CHUNKS, NROWS);
    pair_kernel<<<grid, 256>>>(pred, tg, (float*)d_out);
}

// round 8
// speedup vs baseline: 1.2033x; 1.2033x over previous
#include <cuda_runtime.h>
#include <math.h>

#define NROWS 32
#define NCOLS 512
#define NTILES 16                 // 512 / 32
#define NJOBS  136                // NTILES*(NTILES+1)/2
#define BLOCKS_X 17               // NJOBS / 8 warps per block
#define TOTAL_BLOCKS (BLOCKS_X * NROWS)   // 544
#define TSTW 256                  // tau / w merged table size, domain [0,1]
#define TSG 1024                  // g table size
#define G_MIN (-24.0f)
#define G_RANGE 64.0f             // g domain [-24, 40]
#define NB_TAU 8
#define NB_G 8
#define NB_W 6
#define W_FLOOR 0.001f

// ---------------- device scratch (no allocations allowed) ----------------
__device__ float4 d_tab_tw[TSTW];              // (tau0, dtau, w0, dw)
__device__ float2 d_tab_g[TSG];                // (g0, dg)
__device__ float  d_part_sum[TOTAL_BLOCKS];    // per-block partials (always written)
__device__ int    d_part_cnt[TOTAL_BLOCKS];
__device__ int    d_done;                      // last-block-done counter (reset by last block)

// fast-math activations (table build only; rel_err budget ~1e-3, measured 2e-7)
__device__ __forceinline__ float fsp(float z) {
    return fmaxf(z, 0.0f) + __logf(1.0f + __expf(-fabsf(z)));
}
__device__ __forceinline__ float fsg(float z) {
    return __fdividef(1.0f, 1.0f + __expf(-z));
}

// ---------------- kernel A: build lerp tables ----------------
__global__ void __launch_bounds__(256) table_kernel(
    const float* __restrict__ th_tau, const float* __restrict__ th_g,
    const float* __restrict__ th_w)
{
    int e = blockIdx.x * 256 + threadIdx.x;   // 0 .. TSTW+TSG-1 (= 1279)
    if (e < TSTW) {
        float ct[NB_TAU], cw[NB_W];
#pragma unroll
        for (int i = 0; i < NB_TAU; i++) ct[i] = fsp(th_tau[i]);
#pragma unroll
        for (int i = 0; i < NB_W; i++)   cw[i] = fsp(th_w[i]);
        float h = 1.0f / (float)(TSTW - 1);
        float x = (float)e * h;
        float t0 = 0.f, t1 = 0.f, w0 = 0.f, w1 = 0.f;
#pragma unroll
        for (int i = 0; i < NB_TAU; i++) {
            float sl = 0.5f + 3.5f * (float)i / (float)(NB_TAU - 1);
            float bi = -2.0f + 4.0f * (float)i / (float)(NB_TAU - 1);
            t0 += ct[i] * fsp(fmaf(x,     sl, bi));
            t1 += ct[i] * fsp(fmaf(x + h, sl, bi));
        }
#pragma unroll
        for (int i = 0; i < NB_W; i++) {
            float sl = 0.5f + 3.5f * (float)i / (float)(NB_W - 1);
            float bi = -2.0f + 4.0f * (float)i / (float)(NB_W - 1);
            w0 += cw[i] * fsg(fmaf(x,     sl, bi));
            w1 += cw[i] * fsg(fmaf(x + h, sl, bi));
        }
        d_tab_tw[e] = make_float4(t0, t1 - t0, w0, w1 - w0);
    } else if (e < TSTW + TSG) {
        int i = e - TSTW;
        float cg[NB_G];
#pragma unroll
        for (int u = 0; u < NB_G; u++) cg[u] = fsp(th_g[u]);
        float h = G_RANGE / (float)(TSG - 1);
        float x = G_MIN + (float)i * h;
        float v0 = 0.f, v1 = 0.f;
#pragma unroll
        for (int u = 0; u < NB_G; u++) {
            float sl = 0.5f + 3.5f * (float)u / (float)(NB_G - 1);
            float bi = -2.0f + 4.0f * (float)u / (float)(NB_G - 1);
            v0 += cg[u] * fsp(fmaf(x,     sl, bi));
            v1 += cg[u] * fsp(fmaf(x + h, sl, bi));
        }
        d_tab_g[i] = make_float2(v0, v1 - v0);
    }
}

// ---------------- kernel B: normalization + tiled pair loop + final ----------
__global__ void __launch_bounds__(256, 4) pair_kernel(
    const float* __restrict__ pred, const float* __restrict__ tg,
    float* __restrict__ out)
{
    __shared__ float2 sh_g[TSG];       // 8 KB
    __shared__ float4 sh_tw[TSTW];     // 4 KB
    __shared__ float2 sh_rs[NCOLS];    // 4 KB  (r or NaN-if-masked, s)
    __shared__ float  red_f[8];
    __shared__ float  red_f2[8];
    __shared__ int    red_i[8];
    __shared__ float  bcast[2];
    __shared__ int    sh_last;
    __shared__ float  s_num[32];
    __shared__ float  s_val[32];

    int tid  = threadIdx.x;
    int b    = blockIdx.y;
    int lane = tid & 31, warp = tid >> 5;

    // ---- load this row (2 elems/thread) ----
    const float* tr = tg   + b * NCOLS;
    const float* pr = pred + b * NCOLS;
    float t0 = tr[tid], t1 = tr[tid + 256];
    float p0 = pr[tid], p1 = pr[tid + 256];
    bool  m0 = fabsf(t0 + 1.0f) > 1.00001e-5f;   // ~jnp.isclose(t,-1) negated
    bool  m1 = fabsf(t1 + 1.0f) > 1.00001e-5f;

    // ---- table copy gmem -> smem (overlaps with reduction latency) ----
    {
        const float4* sg = (const float4*)d_tab_g;   float4* dg = (float4*)sh_g;
        dg[tid]       = sg[tid];
        dg[tid + 256] = sg[tid + 256];
        sh_tw[tid]    = d_tab_tw[tid];
    }

    // ---- one-pass masked mean / var (block reduction) ----
    float sum = (m0 ? p0 : 0.f) + (m1 ? p1 : 0.f);
    float ssq = (m0 ? p0 * p0 : 0.f) + (m1 ? p1 * p1 : 0.f);
    int   cnt = (int)m0 + (int)m1;
#pragma unroll
    for (int o = 16; o; o >>= 1) {
        sum += __shfl_xor_sync(0xffffffffu, sum, o);
        ssq += __shfl_xor_sync(0xffffffffu, ssq, o);
        cnt += __shfl_xor_sync(0xffffffffu, cnt, o);
    }
    if (lane == 0) { red_f[warp] = sum; red_f2[warp] = ssq; red_i[warp] = cnt; }
    __syncthreads();
    if (tid == 0) {
        float s = 0.f, q = 0.f; int c = 0;
#pragma unroll
        for (int u = 0; u < 8; u++) { s += red_f[u]; q += red_f2[u]; c += red_i[u]; }
        float denom = fmaxf((float)c, 1.0f);
        float mean  = s / denom;
        float var   = q / denom - mean * mean;
        bcast[0] = mean;
        bcast[1] = rsqrtf(var + 1e-6f);
    }
    __syncthreads();
    float mean = bcast[0], inv = bcast[1];
    const float qnan = __int_as_float(0x7fffffff);
    sh_rs[tid]       = make_float2(m0 ? t0 : qnan, (p0 - mean) * inv);
    sh_rs[tid + 256] = make_float2(m1 ? t1 : qnan, (p1 - mean) * inv);
    __syncthreads();

    // ---- one 32x32 tile job per warp ----
    // jobs enumerate 0 <= ti <= tj < 16; off-diag tiles cover all 32x32 pairs,
    // diagonal tiles keep lane > it (strict upper triangle). Pair loss is
    // symmetric under (i,j) swap so orientation is irrelevant.
    int jb = blockIdx.x * 8 + warp;   // 0 .. 135
    int ti = 0, rem = jb;
    while (rem >= NTILES - ti) { rem -= NTILES - ti; ti++; }
    int tj = ti + rem;
    bool diag = (ti == tj);

    float2 pj = sh_rs[tj * 32 + lane];    // register-resident j side
    const float inv_hg = (float)(TSG - 1) / G_RANGE;
    int ibase = ti * 32;

    float acc = 0.0f; int pcnt = 0;
#pragma unroll 8
    for (int ii = 0; ii < 32; ii++) {
        float2 pi = sh_rs[ibase + ii];    // uniform address -> broadcast LDS.64
        float dr = pi.x - pj.x;
        float ds = pi.y - pj.y;
        bool pos = dr > 0.0f, neg = dr < 0.0f;
        bool keep = (pos | neg) & (!diag | (lane > ii));
        if (keep) {
            float adr = fabsf(dr);
            float tds = pos ? ds : -ds;       // t * ds

            float pt = fminf(adr, 1.0f) * (float)(TSTW - 1);
            int   it = min((int)pt, TSTW - 2);
            float ft = pt - (float)it;
            float4 etw = sh_tw[it];           // one LDS.128: tau + w
            float tau = fmaf(ft, etw.y, etw.x);
            float w   = W_FLOOR + fmaf(ft, etw.w, etw.z);

            float m  = tau - tds;
            float pg = fmaxf((m - G_MIN) * inv_hg, 0.0f);
            int   ig = min((int)pg, TSG - 2);
            float fg = pg - (float)ig;        // frac>1 at top = exact linear ext
            float2 eg = sh_g[ig];
            float g  = fmaf(fg, eg.y, eg.x);

            acc += g * w;
            pcnt += 1;
        }
    }

#pragma unroll
    for (int o = 16; o; o >>= 1) {
        acc  += __shfl_xor_sync(0xffffffffu, acc, o);
        pcnt += __shfl_xor_sync(0xffffffffu, pcnt, o);
    }
    __syncthreads();   // red_f / red_i reuse
    if (lane == 0) { red_f[warp] = acc; red_i[warp] = pcnt; }
    __syncthreads();
    if (tid == 0) {
        float bs = 0.0f; int bc = 0;
#pragma unroll
        for (int u = 0; u < 8; u++) { bs += red_f[u]; bc += red_i[u]; }
        int slot = b * BLOCKS_X + blockIdx.x;
        d_part_sum[slot] = bs;
        d_part_cnt[slot] = bc;
        __threadfence();
        int old = atomicAdd(&d_done, 1);
        sh_last = (old == TOTAL_BLOCKS - 1) ? 1 : 0;
    }
    __syncthreads();

    // ---- last block performs the final reduction (544 partials) ----
    if (sh_last) {
        __threadfence();   // acquire: partials of all other blocks now visible
        volatile float* vs = d_part_sum;
        volatile int*   vc = d_part_cnt;
        int row = tid >> 3;            // 32 rows x 8 lanes
        int sub = tid & 7;             // lane sub handles chunks sub, sub+8, (16 if sub==0)
        int base = row * BLOCKS_X;
        float ps = vs[base + sub] + vs[base + sub + 8];
        int   pc = vc[base + sub] + vc[base + sub + 8];
        if (sub == 0) { ps += vs[base + 16]; pc += vc[base + 16]; }
#pragma unroll
        for (int o = 4; o; o >>= 1) {
            ps += __shfl_xor_sync(0xffffffffu, ps, o);
            pc += __shfl_xor_sync(0xffffffffu, pc, o);
        }
        if (sub == 0) {
            float denom = fmaxf((float)pc, 1.0f);
            float rl    = ps / denom;
            float valid = (pc > 0) ? 1.0f : 0.0f;
            s_num[row] = rl * valid;
            s_val[row] = valid;
        }
        __syncthreads();
        if (tid < 32) {
            float n = s_num[tid], v = s_val[tid];
#pragma unroll
            for (int o = 16; o; o >>= 1) {
                n += __shfl_xor_sync(0xffffffffu, n, o);
                v += __shfl_xor_sync(0xffffffffu, v, o);
            }
            if (tid == 0) {
                out[0] = n / fmaxf(v, 1.0f);
                d_done = 0;            // reset for next graph replay (deterministic)
            }
        }
    }
}

// ---------------- launch ----------------
extern "C" void kernel_launch(void* const* d_in, const int* in_sizes, int n_in,
                              void* d_out, int out_size) {
    const float* pred   = (const float*)d_in[0];
    const float* tg     = (const float*)d_in[1];
    const float* th_tau = (const float*)d_in[2];
    const float* th_g   = (const float*)d_in[3];
    const float* th_w   = (const float*)d_in[4];

    table_kernel<<<(TSTW + TSG) / 256, 256>>>(th_tau, th_g, th_w);
    dim3 grid(BLOCKS_X, NROWS);
    pair_kernel<<<grid, 256>>>(pred, tg, (float*)d_out);
}